// round 15
// baseline (speedup 1.0000x reference)
#include <cuda_runtime.h>
#include <cuda_bf16.h>
#include <math_constants.h>
#include <cstdint>

#define BATCH 8
#define CH 128
#define NT 4096
#define NF 2049
#define MROWS (BATCH * NF)   // 16392
#define LOGN 12
#define SQRTN 64.0f
#define FP 2176              // padded F: 17*128 = 34*64
#define NEG_INF __int_as_float(0xff800000)
#define SCALE 0.08838834764831845f   // 1/sqrt(128)

// ---------------- scratch (device globals; no allocation allowed) ----------------
__device__ float2 g_X[(size_t)MROWS * CH];    // x_fft   (B,F,C)
__device__ float2 g_Kp[(size_t)MROWS * CH];   // K       (B,F,C)
__device__ float2 g_Vp[(size_t)MROWS * CH];   // V       (B,F,C)
__device__ float2 g_ctx[(size_t)MROWS * CH];  // context (B,F,C)
__device__ float  g_energy[MROWS];
__device__ float  g_norm[MROWS];
__device__ float  g_med[BATCH];
__device__ float  g_qv[2];
__device__ float  g_thr[1];
__device__ float2 g_TW[NT / 2];               // exp(-2*pi*i*k/N)
__device__ float  g_WT[2 * CH * CH];          // W_K^T then W_V^T
__device__ unsigned g_hist[65536];
__device__ int    g_bk[2];

// GEMM staging (fp32 values PRE-ROUNDED to tf32 precision by producers)
__device__ __align__(16) float g_Qf [(size_t)BATCH * FP * 256];  // scale*[Qr|Qi]
__device__ __align__(16) float g_Krf[(size_t)BATCH * FP * 256];  // [Kr|-Ki]
__device__ __align__(16) float g_Kif[(size_t)BATCH * FP * 256];  // [Ki|Kr]
__device__ __align__(16) float g_Vf [(size_t)BATCH * FP * 256];  // [Vr|Vi]
__device__ __align__(16) float g_VfT[(size_t)BATCH * 256 * FP];  // V transposed (n-major)
__device__ __align__(16) float g_LOG[(size_t)BATCH * FP * FP];   // logits scale*|s|
__device__ __align__(16) float g_P  [(size_t)BATCH * FP * FP];   // normalized softmax (tf32-rounded)
__device__ __align__(16) float g_ctxr[(size_t)BATCH * FP * 256]; // [ctx_r|ctx_i]

// ---------------- helpers ----------------
__device__ __forceinline__ float tf32r(float x) {
    uint32_t u;
    asm("cvt.rna.tf32.f32 %0, %1;" : "=r"(u) : "f"(x));
    return __uint_as_float(u);
}

__device__ __forceinline__ void mma_tf32(float* c,
    float a0, float a1, float a2, float a3, float b0, float b1) {
    asm volatile(
        "mma.sync.aligned.m16n8k8.row.col.f32.tf32.tf32.f32 "
        "{%0,%1,%2,%3},{%4,%5,%6,%7},{%8,%9},{%0,%1,%2,%3};\n"
        : "+f"(c[0]), "+f"(c[1]), "+f"(c[2]), "+f"(c[3])
        : "r"(__float_as_uint(a0)), "r"(__float_as_uint(a1)),
          "r"(__float_as_uint(a2)), "r"(__float_as_uint(a3)),
          "r"(__float_as_uint(b0)), "r"(__float_as_uint(b1)));
}

__device__ __forceinline__ void cp16(uint32_t saddr, const void* gptr) {
    asm volatile("cp.async.cg.shared.global [%0], [%1], 16;\n"
                 :: "r"(saddr), "l"(gptr));
}
__device__ __forceinline__ void cp_commit() {
    asm volatile("cp.async.commit_group;\n");
}
template <int N>
__device__ __forceinline__ void cp_wait() {
    asm volatile("cp.async.wait_group %0;\n" :: "n"(N));
}

__device__ __forceinline__ float2 cmul(float2 a, float2 b) {
    return make_float2(a.x * b.x - a.y * b.y, a.x * b.y + a.y * b.x);
}

// base-4 digit reversal of a 12-bit index: bit-reverse then swap bit pairs
__device__ __forceinline__ int rev4_12(int n) {
    unsigned r = __brev((unsigned)n) >> 20;
    return (int)(((r & 0x555u) << 1) | ((r >> 1) & 0x555u));
}

// ---------------- init: twiddles + transposed weights ----------------
__global__ void k_init(const float* __restrict__ WK, const float* __restrict__ WV) {
    int i = blockIdx.x * blockDim.x + threadIdx.x;
    if (i < NT / 2) {
        float s, c;
        sincospif(2.0f * (float)i / (float)NT, &s, &c);
        g_TW[i] = make_float2(c, -s);
    }
    if (i < CH * CH) {
        int cc = i >> 7, cp = i & 127;
        g_WT[cc * CH + cp] = WK[cp * CH + cc];
        g_WT[CH * CH + cc * CH + cp] = WV[cp * CH + cc];
    }
}

// ---------------- shared-memory radix-4 FFT (4096 = 4^6), 256 threads ----------------
template <bool INV>
__device__ __forceinline__ void fft4096_r4(float2* sh, int tid) {
    #pragma unroll
    for (int s = 0; s < 6; s++) {
        int mh = 1 << (2 * s);              // 1,4,16,64,256,1024
        int step = NT >> (2 * s + 2);       // NT/(4*mh)
        #pragma unroll
        for (int it = 0; it < 4; it++) {
            int idx = tid + it * 256;       // 0..1023 butterflies
            int j = idx & (mh - 1);
            int base = ((idx - j) << 2) + j;
            float2 w1 = g_TW[j * step];
            float2 w2 = g_TW[2 * j * step];
            if (INV) { w1.y = -w1.y; w2.y = -w2.y; }
            float2 w3 = cmul(w1, w2);
            float2 B0 = sh[base];
            float2 B1 = cmul(sh[base + mh], w1);
            float2 B2 = cmul(sh[base + 2 * mh], w2);
            float2 B3 = cmul(sh[base + 3 * mh], w3);
            float2 t0 = make_float2(B0.x + B2.x, B0.y + B2.y);
            float2 t1 = make_float2(B0.x - B2.x, B0.y - B2.y);
            float2 t2 = make_float2(B1.x + B3.x, B1.y + B3.y);
            float2 t3 = make_float2(B1.x - B3.x, B1.y - B3.y);
            // rotate t3 by -i (fwd) / +i (inv)
            float2 t3r = INV ? make_float2(-t3.y, t3.x) : make_float2(t3.y, -t3.x);
            sh[base]          = make_float2(t0.x + t2.x, t0.y + t2.y);
            sh[base + 2 * mh] = make_float2(t0.x - t2.x, t0.y - t2.y);
            sh[base + mh]     = make_float2(t1.x + t3r.x, t1.y + t3r.y);
            sh[base + 3 * mh] = make_float2(t1.x - t3r.x, t1.y - t3r.y);
        }
        __syncthreads();
    }
}

__global__ void k_rfft(const float* __restrict__ x) {
    __shared__ float2 sh[NT];
    int row = blockIdx.x;
    int b = row >> 7, c = row & 127;
    const float* xp = x + (size_t)row * NT;
    for (int n = threadIdx.x; n < NT; n += blockDim.x)
        sh[rev4_12(n)] = make_float2(xp[n], 0.f);
    __syncthreads();
    fft4096_r4<false>(sh, threadIdx.x);
    const float inv = 1.0f / SQRTN;
    for (int f = threadIdx.x; f < NF; f += blockDim.x) {
        float2 v = sh[f];
        g_X[((size_t)b * NF + f) * CH + c] = make_float2(v.x * inv, v.y * inv);
    }
}

// ---------------- K/V projection ----------------
__global__ void k_proj(const float* __restrict__ bK, const float* __restrict__ bV) {
    __shared__ float2 xs[16 * CH];
    int r0 = blockIdx.x * 16;
    int tid = threadIdx.x;
    for (int idx = tid; idx < 16 * CH; idx += 256) {
        int r = idx >> 7, c = idx & 127;
        int gr = r0 + r;
        xs[idx] = (gr < MROWS) ? g_X[(size_t)gr * CH + c] : make_float2(0.f, 0.f);
    }
    __syncthreads();
    int cp = tid & 127;
    int half = tid >> 7;
    float kr[8] = {0}, ki[8] = {0}, vr[8] = {0}, vi[8] = {0};
    const float* wk = g_WT;
    const float* wv = g_WT + CH * CH;
    for (int c = 0; c < CH; c++) {
        float a = __ldg(wk + c * CH + cp);
        float bb = __ldg(wv + c * CH + cp);
        #pragma unroll
        for (int r = 0; r < 8; r++) {
            float2 xv = xs[(half * 8 + r) * CH + c];
            kr[r] += xv.x * a;  ki[r] += xv.y * a;
            vr[r] += xv.x * bb; vi[r] += xv.y * bb;
        }
    }
    #pragma unroll
    for (int r = 0; r < 8; r++) {
        int gr = r0 + half * 8 + r;
        if (gr < MROWS) {
            if (gr % NF == 0) { kr[r] += SQRTN * bK[cp]; vr[r] += SQRTN * bV[cp]; }
            g_Kp[(size_t)gr * CH + cp] = make_float2(kr[r], ki[r]);
            g_Vp[(size_t)gr * CH + cp] = make_float2(vr[r], vi[r]);
        }
    }
}

// ---------------- pack staging buffers (tf32-pre-rounded fp32; coalesced) ----------------
__global__ void k_pack() {
    int f = blockIdx.x, b = blockIdx.y, n = threadIdx.x;   // n in [0,256)
    size_t o = ((size_t)b * FP + f) * 256 + n;
    float q = 0.f, kr = 0.f, ki = 0.f, vv = 0.f;
    if (f < NF) {
        int c = n & 127;
        size_t src = ((size_t)b * NF + f) * CH + c;
        float2 X = g_X[src], K = g_Kp[src], V = g_Vp[src];
        if (n < 128) { q = X.x; kr = K.x;  ki = K.y; vv = V.x; }
        else         { q = X.y; kr = -K.y; ki = K.x; vv = V.y; }
    }
    g_Qf[o]  = tf32r(q * SCALE);
    g_Krf[o] = tf32r(kr);
    g_Kif[o] = tf32r(ki);
    g_Vf[o]  = tf32r(vv);
}

// ---------------- tiled transpose of V: g_Vf (FPx256) -> g_VfT (256xFP) ----------------
__global__ void k_vt() {
    __shared__ float t[32][33];
    int b = blockIdx.z;
    int f0 = blockIdx.x * 32, n0 = blockIdx.y * 32;
    int x = threadIdx.x, y = threadIdx.y;    // block (32, 8)
    #pragma unroll
    for (int i = 0; i < 32; i += 8)
        t[y + i][x] = g_Vf[((size_t)b * FP + f0 + y + i) * 256 + n0 + x];
    __syncthreads();
    #pragma unroll
    for (int i = 0; i < 32; i += 8)
        g_VfT[((size_t)b * 256 + n0 + y + i) * FP + f0 + x] = t[x][y + i];
}

// ---------------- energy / median / quantile ----------------
__global__ void k_energy() {
    int row = blockIdx.x;
    int c = threadIdx.x;
    float2 v = g_X[(size_t)row * CH + c];
    float e = v.x * v.x + v.y * v.y;
    #pragma unroll
    for (int o = 16; o; o >>= 1) e += __shfl_xor_sync(~0u, e, o);
    __shared__ float ws[4];
    if ((c & 31) == 0) ws[c >> 5] = e;
    __syncthreads();
    if (c == 0) g_energy[row] = ws[0] + ws[1] + ws[2] + ws[3];
}

__global__ void k_median() {
    int i = blockIdx.x * blockDim.x + threadIdx.x;
    if (i >= MROWS) return;
    int b = i / NF;
    float e = g_energy[i];
    const float* eb = g_energy + b * NF;
    int less = 0, leq = 0;
    for (int f = 0; f < NF; f++) {
        float v = __ldg(eb + f);
        less += (v < e);
        leq  += (v <= e);
    }
    if (less <= (NF / 2) && (NF / 2) < leq) g_med[b] = e;
}

__global__ void k_norm() {
    int i = blockIdx.x * blockDim.x + threadIdx.x;
    if (i < MROWS) g_norm[i] = g_energy[i] / (g_med[i / NF] + 1e-6f);
}

// histogram over top-16 bits of the (non-negative) float bit pattern: monotonic buckets
__global__ void k_hzero() {
    int i = blockIdx.x * blockDim.x + threadIdx.x;
    if (i < 65536) g_hist[i] = 0;
}
__global__ void k_hist() {
    int i = blockIdx.x * blockDim.x + threadIdx.x;
    if (i < MROWS) atomicAdd(&g_hist[__float_as_uint(g_norm[i]) >> 16], 1u);
}
__global__ void k_hscan(const float* __restrict__ thp) {
    __shared__ unsigned ps[1024];
    int t = threadIdx.x;
    unsigned s = 0;
    #pragma unroll 4
    for (int j = 0; j < 64; j++) s += g_hist[t * 64 + j];
    ps[t] = s;
    __syncthreads();
    for (int off = 1; off < 1024; off <<= 1) {
        unsigned v = (t >= off) ? ps[t - off] : 0;
        __syncthreads();
        ps[t] += v;
        __syncthreads();
    }
    unsigned run = (t == 0) ? 0u : ps[t - 1];
    float q = thp[0];
    int k0 = (int)floorf(q * (float)(MROWS - 1));
    unsigned r0 = (unsigned)k0, r1 = (unsigned)(k0 + 1);
    for (int j = 0; j < 64; j++) {
        unsigned c = g_hist[t * 64 + j];
        if (r0 >= run && r0 < run + c) g_bk[0] = t * 64 + j;
        if (r1 >= run && r1 < run + c) g_bk[1] = t * 64 + j;
        run += c;
    }
}
__global__ void k_qsel(const float* __restrict__ thp) {
    int i = blockIdx.x * blockDim.x + threadIdx.x;
    if (i >= MROWS) return;
    float v = g_norm[i];
    int bb = (int)(__float_as_uint(v) >> 16);
    int bk0 = g_bk[0], bk1 = g_bk[1];
    if (bb != bk0 && bb != bk1) return;
    float q = thp[0];
    int k = (int)floorf(q * (float)(MROWS - 1));
    int less = 0, leq = 0;
    for (int j = 0; j < MROWS; j++) {
        float u = __ldg(g_norm + j);
        less += (u < v);
        leq  += (u <= v);
    }
    if (less <= k && k < leq)         g_qv[0] = v;
    if (less <= k + 1 && k + 1 < leq) g_qv[1] = v;
}

__global__ void k_thr(const float* __restrict__ thp) {
    float q = thp[0];
    float h = q * (float)(MROWS - 1);
    float k = floorf(h);
    g_thr[0] = g_qv[0] + (h - k) * (g_qv[1] - g_qv[0]);
}

// ---------------- scores GEMM: logits = scale*|Q K^T| (1x tf32, 3-stage cp.async) ----------------
// BM=128, BN=64, BK=16. 8 warps as 4x2, warp tile 32x32. Single sync per k-tile.
#define SC_SMEM ((3 * (2560 + 1280 + 1280)) * 4)   // 61440 B
__global__ void __launch_bounds__(256, 2) k_scores() {
    extern __shared__ __align__(16) float dsm[];
    float* As  = dsm;                 // 3 x (128 x 20)
    float* Brs = dsm + 3 * 2560;      // 3 x (64 x 20)
    float* Bis = dsm + 3 * 2560 + 3 * 1280;
    int b = blockIdx.z;
    int row0 = blockIdx.y * 128, col0 = blockIdx.x * 64;
    const float* Qb  = g_Qf  + ((size_t)b * FP + row0) * 256;
    const float* Krb = g_Krf + ((size_t)b * FP + col0) * 256;
    const float* Kib = g_Kif + ((size_t)b * FP + col0) * 256;
    int tid = threadIdx.x, w = tid >> 5, lane = tid & 31;
    int g = lane >> 2, t = lane & 3;
    int wr = (w & 3) * 32, wc = (w >> 2) * 32;
    float sr[2][4][4], si[2][4][4];
    #pragma unroll
    for (int rt = 0; rt < 2; rt++)
        #pragma unroll
        for (int nt = 0; nt < 4; nt++)
            #pragma unroll
            for (int e = 0; e < 4; e++) { sr[rt][nt][e] = 0.f; si[rt][nt][e] = 0.f; }

    int lr = tid >> 2, lc = (tid & 3) * 4;
    uint32_t aA  = (uint32_t)__cvta_generic_to_shared(As);
    uint32_t aBr = (uint32_t)__cvta_generic_to_shared(Brs);
    uint32_t aBi = (uint32_t)__cvta_generic_to_shared(Bis);

    auto issue = [&](int kt) {
        int s = kt % 3, k0 = kt * 16;
        uint32_t dA = aA + (uint32_t)(s * 2560 + lr * 20 + lc) * 4;
        cp16(dA,               Qb + (size_t)lr * 256 + k0 + lc);
        cp16(dA + 64 * 20 * 4, Qb + (size_t)(lr + 64) * 256 + k0 + lc);
        cp16(aBr + (uint32_t)(s * 1280 + lr * 20 + lc) * 4, Krb + (size_t)lr * 256 + k0 + lc);
        cp16(aBi + (uint32_t)(s * 1280 + lr * 20 + lc) * 4, Kib + (size_t)lr * 256 + k0 + lc);
        cp_commit();
    };

    issue(0);
    issue(1);
    for (int kt = 0; kt < 16; kt++) {
        if (kt == 15) cp_wait<0>(); else cp_wait<1>();
        __syncthreads();
        if (kt + 2 < 16) issue(kt + 2);
        const float* Ac  = As  + (kt % 3) * 2560;
        const float* Brc = Brs + (kt % 3) * 1280;
        const float* Bic = Bis + (kt % 3) * 1280;
        #pragma unroll
        for (int k8 = 0; k8 < 16; k8 += 8) {
            float a0[2], a1[2], a2[2], a3[2];
            #pragma unroll
            for (int rt = 0; rt < 2; rt++) {
                int r = wr + rt * 16 + g;
                a0[rt] = Ac[r * 20 + k8 + t];
                a1[rt] = Ac[(r + 8) * 20 + k8 + t];
                a2[rt] = Ac[r * 20 + k8 + t + 4];
                a3[rt] = Ac[(r + 8) * 20 + k8 + t + 4];
            }
            #pragma unroll
            for (int nt = 0; nt < 4; nt++) {
                int n = wc + nt * 8 + g;
                float br0 = Brc[n * 20 + k8 + t], br1 = Brc[n * 20 + k8 + t + 4];
                float bi0 = Bic[n * 20 + k8 + t], bi1 = Bic[n * 20 + k8 + t + 4];
                #pragma unroll
                for (int rt = 0; rt < 2; rt++) {
                    mma_tf32(sr[rt][nt], a0[rt], a1[rt], a2[rt], a3[rt], br0, br1);
                    mma_tf32(si[rt][nt], a0[rt], a1[rt], a2[rt], a3[rt], bi0, bi1);
                }
            }
        }
    }
    float* L = g_LOG + ((size_t)b * FP + row0) * FP + col0;
    #pragma unroll
    for (int rt = 0; rt < 2; rt++)
        #pragma unroll
        for (int nt = 0; nt < 4; nt++)
            #pragma unroll
            for (int half = 0; half < 2; half++) {
                int r = wr + rt * 16 + g + half * 8;
                int c0 = wc + nt * 8 + t * 2;
                float x0 = sr[rt][nt][half * 2 + 0], y0 = si[rt][nt][half * 2 + 0];
                float x1 = sr[rt][nt][half * 2 + 1], y1 = si[rt][nt][half * 2 + 1];
                float v0 = sqrtf(x0 * x0 + y0 * y0);
                float v1 = sqrtf(x1 * x1 + y1 * y1);
                if (col0 + c0 >= NF)     v0 = NEG_INF;
                if (col0 + c0 + 1 >= NF) v1 = NEG_INF;
                *(float2*)&L[(size_t)r * FP + c0] = make_float2(v0, v1);
            }
}

// ---------------- row softmax, normalized, store tf32-rounded fp32 ----------------
__global__ void __launch_bounds__(256) k_softmax() {
    int f = blockIdx.x, b = blockIdx.y, tid = threadIdx.x;
    float* Pr = g_P + ((size_t)b * FP + f) * FP;
    if (f >= NF) {
        for (int i = tid; i < FP; i += 256) Pr[i] = 0.f;
        return;
    }
    const float* Lr = g_LOG + ((size_t)b * FP + f) * FP;
    int w = tid >> 5, lane = tid & 31;
    __shared__ float red[8];
    float v[9];
    float m = NEG_INF;
    #pragma unroll
    for (int i = 0; i < 9; i++) {
        int idx = tid + i * 256;
        v[i] = (idx < FP) ? Lr[idx] : NEG_INF;
        m = fmaxf(m, v[i]);
    }
    #pragma unroll
    for (int o = 16; o; o >>= 1) m = fmaxf(m, __shfl_xor_sync(~0u, m, o));
    if (lane == 0) red[w] = m;
    __syncthreads();
    float M = red[0];
    #pragma unroll
    for (int i = 1; i < 8; i++) M = fmaxf(M, red[i]);
    float s = 0.f;
    #pragma unroll
    for (int i = 0; i < 9; i++) {
        float e = __expf(v[i] - M);
        v[i] = e;
        s += e;
    }
    #pragma unroll
    for (int o = 16; o; o >>= 1) s += __shfl_xor_sync(~0u, s, o);
    __syncthreads();
    if (lane == 0) red[w] = s;
    __syncthreads();
    float S = 0.f;
    #pragma unroll
    for (int i = 0; i < 8; i++) S += red[i];
    float inv = 1.0f / S;
    #pragma unroll
    for (int i = 0; i < 9; i++) {
        int idx = tid + i * 256;
        if (idx < FP) Pr[idx] = tf32r(v[i] * inv);
    }
}

// ---------------- PV GEMM: ctx = P * Vt^T (1x tf32, pre-rounded) ----------------
// BM=64, BN=256 (full N -> P read exactly once). BK=16, 3-stage cp.async.
#define PV_SMEM ((3 * (64 * 20 + 256 * 20)) * 4)
__global__ void __launch_bounds__(256) k_pv() {
    extern __shared__ __align__(16) float dsm[];
    float* As = dsm;                 // 3 x (64 x 20)
    float* Bs = dsm + 3 * 1280;      // 3 x (256 x 20)
    int b = blockIdx.z, row0 = blockIdx.y * 64;
    const float* Pb  = g_P   + ((size_t)b * FP + row0) * FP;
    const float* Vtb = g_VfT + (size_t)b * 256 * FP;
    int tid = threadIdx.x, w = tid >> 5, lane = tid & 31;
    int g = lane >> 2, t = lane & 3;
    int wr = (w & 1) * 32, wc = (w >> 1) * 64;
    float acc[2][8][4];
    #pragma unroll
    for (int rt = 0; rt < 2; rt++)
        #pragma unroll
        for (int nt = 0; nt < 8; nt++)
            #pragma unroll
            for (int e = 0; e < 4; e++) acc[rt][nt][e] = 0.f;

    int lr = tid >> 2, lc = (tid & 3) * 4;   // lr in [0,64), lc in {0,4,8,12}
    uint32_t aA = (uint32_t)__cvta_generic_to_shared(As);
    uint32_t aB = (uint32_t)__cvta_generic_to_shared(Bs);

    auto issue = [&](int kt) {
        int s = kt % 3, k0 = kt * 16;
        cp16(aA + (uint32_t)(s * 1280 + lr * 20 + lc) * 4,
             Pb + (size_t)lr * FP + k0 + lc);
        #pragma unroll
        for (int i = 0; i < 4; i++) {
            int n = lr + 64 * i;
            cp16(aB + (uint32_t)(s * 5120 + n * 20 + lc) * 4,
                 Vtb + (size_t)n * FP + k0 + lc);
        }
        cp_commit();
    };

    const int NK = FP / 16;   // 136
    issue(0);
    issue(1);
    for (int kt = 0; kt < NK; kt++) {
        if (kt == NK - 1) cp_wait<0>(); else cp_wait<1>();
        __syncthreads();
        if (kt + 2 < NK) issue(kt + 2);
        const float* Ac = As + (kt % 3) * 1280;
        const float* Bc = Bs + (kt % 3) * 5120;
        #pragma unroll
        for (int k8 = 0; k8 < 16; k8 += 8) {
            float a0[2], a1[2], a2[2], a3[2];
            #pragma unroll
            for (int rt = 0; rt < 2; rt++) {
                int r = wr + rt * 16 + g;
                a0[rt] = Ac[r * 20 + k8 + t];
                a1[rt] = Ac[(r + 8) * 20 + k8 + t];
                a2[rt] = Ac[r * 20 + k8 + t + 4];
                a3[rt] = Ac[(r + 8) * 20 + k8 + t + 4];
            }
            #pragma unroll
            for (int nt = 0; nt < 8; nt++) {
                int n = wc + nt * 8 + g;
                float b0 = Bc[n * 20 + k8 + t];
                float b1 = Bc[n * 20 + k8 + t + 4];
                #pragma unroll
                for (int rt = 0; rt < 2; rt++)
                    mma_tf32(acc[rt][nt], a0[rt], a1[rt], a2[rt], a3[rt], b0, b1);
            }
        }
    }
    float* O = g_ctxr + ((size_t)b * FP + row0) * 256;
    #pragma unroll
    for (int rt = 0; rt < 2; rt++)
        #pragma unroll
        for (int nt = 0; nt < 8; nt++)
            #pragma unroll
            for (int half = 0; half < 2; half++) {
                int r = wr + rt * 16 + g + half * 8;
                int c0 = wc + nt * 8 + t * 2;
                *(float2*)&O[(size_t)r * 256 + c0] =
                    make_float2(acc[rt][nt][half * 2 + 0], acc[rt][nt][half * 2 + 1]);
            }
}

// ---------------- combine: high-freq residual + pack into g_ctx ----------------
__global__ void k_combine(const float* __restrict__ whigh) {
    int f = blockIdx.x, b = blockIdx.y, c = threadIdx.x;   // c in [0,128)
    size_t ro = ((size_t)b * FP + f) * 256;
    float cr = g_ctxr[ro + c];
    float ci = g_ctxr[ro + 128 + c];
    if (g_norm[b * NF + f] > g_thr[0]) {
        float2 xv = g_X[((size_t)b * NF + f) * CH + c];
        float wrr = whigh[c * 2], wi = whigh[c * 2 + 1];
        cr += xv.x * wrr - xv.y * wi;
        ci += xv.x * wi + xv.y * wrr;
    }
    g_ctx[((size_t)b * NF + f) * CH + c] = make_float2(cr, ci);
}

// ---------------- irfft (radix-4) ----------------
__global__ void k_irfft(float* __restrict__ out) {
    __shared__ float2 sh[NT];
    int row = blockIdx.x;
    int b = row >> 7, c = row & 127;
    size_t base = ((size_t)b * NF) * CH + c;
    for (int n = threadIdx.x; n < NT; n += blockDim.x) {
        float2 v;
        if (n == 0)            { v = g_ctx[base]; v.y = 0.f; }
        else if (n < NT / 2)   { v = g_ctx[base + (size_t)n * CH]; }
        else if (n == NT / 2)  { v = g_ctx[base + (size_t)(NT / 2) * CH]; v.y = 0.f; }
        else                   { v = g_ctx[base + (size_t)(NT - n) * CH]; v.y = -v.y; }
        sh[rev4_12(n)] = v;
    }
    __syncthreads();
    fft4096_r4<true>(sh, threadIdx.x);
    float* op = out + (size_t)row * NT;
    const float inv = 1.0f / SQRTN;
    for (int n = threadIdx.x; n < NT; n += blockDim.x)
        op[n] = sh[n].x * inv;
}

// ---------------- launch ----------------
extern "C" void kernel_launch(void* const* d_in, const int* in_sizes, int n_in,
                              void* d_out, int out_size) {
    const float* x   = (const float*)d_in[0];
    const float* WK  = (const float*)d_in[1];
    const float* bK  = (const float*)d_in[2];
    const float* WV  = (const float*)d_in[3];
    const float* bV  = (const float*)d_in[4];
    const float* wh  = (const float*)d_in[5];
    const float* thp = (const float*)d_in[6];
    float* out = (float*)d_out;

    cudaFuncSetAttribute(k_scores, cudaFuncAttributeMaxDynamicSharedMemorySize, SC_SMEM);
    cudaFuncSetAttribute(k_pv, cudaFuncAttributeMaxDynamicSharedMemorySize, PV_SMEM);

    k_init<<<64, 256>>>(WK, WV);
    k_rfft<<<BATCH * CH, 256>>>(x);
    k_proj<<<(MROWS + 15) / 16, 256>>>(bK, bV);
    k_pack<<<dim3(FP, BATCH), 256>>>();
    k_vt<<<dim3(FP / 32, 256 / 32, BATCH), dim3(32, 8)>>>();
    k_scores<<<dim3(FP / 64, FP / 128, BATCH), 256, SC_SMEM>>>();
    k_energy<<<MROWS, 128>>>();
    k_median<<<(MROWS + 255) / 256, 256>>>();
    k_norm<<<(MROWS + 255) / 256, 256>>>();
    k_hzero<<<256, 256>>>();
    k_hist<<<(MROWS + 255) / 256, 256>>>();
    k_hscan<<<1, 1024>>>(thp);
    k_qsel<<<(MROWS + 255) / 256, 256>>>(thp);
    k_thr<<<1, 1>>>(thp);
    k_softmax<<<dim3(FP, BATCH), 256>>>();
    k_pv<<<dim3(1, FP / 64, BATCH), 256, PV_SMEM>>>();
    k_combine<<<dim3(NF, BATCH), 128>>>(wh);
    k_irfft<<<BATCH * CH, 256>>>(out);
}

// round 16
// speedup vs baseline: 1.4114x; 1.4114x over previous
#include <cuda_runtime.h>
#include <cuda_bf16.h>
#include <math_constants.h>
#include <cstdint>

#define BATCH 8
#define CH 128
#define NT 4096
#define NF 2049
#define MROWS (BATCH * NF)   // 16392
#define LOGN 12
#define SQRTN 64.0f
#define FP 2176              // padded F: 17*128 = 34*64
#define SC_COLS 2112         // 33*64: key cols actually computed (>=NF masked)
#define NEG_INF __int_as_float(0xff800000)
#define SCALE 0.08838834764831845f   // 1/sqrt(128)

// ---------------- scratch (device globals; no allocation allowed) ----------------
__device__ float2 g_X[(size_t)MROWS * CH];    // x_fft   (B,F,C)
__device__ float2 g_Kp[(size_t)MROWS * CH];   // K       (B,F,C)
__device__ float2 g_Vp[(size_t)MROWS * CH];   // V       (B,F,C)
__device__ float2 g_ctx[(size_t)MROWS * CH];  // context (B,F,C)
__device__ float  g_energy[MROWS];
__device__ float  g_norm[MROWS];
__device__ float  g_med[BATCH];
__device__ float  g_qv[2];
__device__ float  g_thr[1];
__device__ float2 g_TW[NT / 2];               // exp(-2*pi*i*k/N)
__device__ float  g_WT[2 * CH * CH];          // W_K^T then W_V^T
__device__ unsigned g_hist[65536];
__device__ int    g_bk[2];

// GEMM staging (fp32 values PRE-ROUNDED to tf32 precision by producers)
__device__ __align__(16) float g_Qf [(size_t)BATCH * FP * 256];  // scale*[Qr|Qi]
__device__ __align__(16) float g_Krf[(size_t)BATCH * FP * 256];  // [Kr|-Ki]
__device__ __align__(16) float g_Kif[(size_t)BATCH * FP * 256];  // [Ki|Kr]
__device__ __align__(16) float g_Vf [(size_t)BATCH * FP * 256];  // [Vr|Vi]
__device__ __align__(16) float g_VfT[(size_t)BATCH * 256 * FP];  // V transposed (n-major)
__device__ __align__(16) float g_LOG[(size_t)BATCH * FP * FP];   // logits scale*|s|
__device__ __align__(16) float g_P  [(size_t)BATCH * FP * FP];   // normalized softmax (tf32-rounded)
__device__ __align__(16) float g_ctxr[(size_t)BATCH * FP * 256]; // [ctx_r|ctx_i]

// ---------------- helpers ----------------
__device__ __forceinline__ float tf32r(float x) {
    uint32_t u;
    asm("cvt.rna.tf32.f32 %0, %1;" : "=r"(u) : "f"(x));
    return __uint_as_float(u);
}

__device__ __forceinline__ void mma_tf32(float* c,
    float a0, float a1, float a2, float a3, float b0, float b1) {
    asm volatile(
        "mma.sync.aligned.m16n8k8.row.col.f32.tf32.tf32.f32 "
        "{%0,%1,%2,%3},{%4,%5,%6,%7},{%8,%9},{%0,%1,%2,%3};\n"
        : "+f"(c[0]), "+f"(c[1]), "+f"(c[2]), "+f"(c[3])
        : "r"(__float_as_uint(a0)), "r"(__float_as_uint(a1)),
          "r"(__float_as_uint(a2)), "r"(__float_as_uint(a3)),
          "r"(__float_as_uint(b0)), "r"(__float_as_uint(b1)));
}

__device__ __forceinline__ void cp16(uint32_t saddr, const void* gptr) {
    asm volatile("cp.async.cg.shared.global [%0], [%1], 16;\n"
                 :: "r"(saddr), "l"(gptr));
}
__device__ __forceinline__ void cp_commit() {
    asm volatile("cp.async.commit_group;\n");
}
template <int N>
__device__ __forceinline__ void cp_wait() {
    asm volatile("cp.async.wait_group %0;\n" :: "n"(N));
}

// ---------------- init: twiddles + transposed weights ----------------
__global__ void k_init(const float* __restrict__ WK, const float* __restrict__ WV) {
    int i = blockIdx.x * blockDim.x + threadIdx.x;
    if (i < NT / 2) {
        float s, c;
        sincospif(2.0f * (float)i / (float)NT, &s, &c);
        g_TW[i] = make_float2(c, -s);
    }
    if (i < CH * CH) {
        int cc = i >> 7, cp = i & 127;
        g_WT[cc * CH + cp] = WK[cp * CH + cc];
        g_WT[CH * CH + cc * CH + cp] = WV[cp * CH + cc];
    }
}

// ---------------- shared-memory radix-2 FFT ----------------
template <bool INV>
__device__ __forceinline__ void fft4096(float2* sh, int tid, int nthreads) {
    #pragma unroll 1
    for (int s = 1; s <= LOGN; s++) {
        int mh = 1 << (s - 1);
        for (int k = tid; k < NT / 2; k += nthreads) {
            int j = k & (mh - 1);
            int base = ((k - j) << 1) + j;
            float2 w = g_TW[j << (LOGN - s)];
            if (INV) w.y = -w.y;
            float2 a = sh[base];
            float2 bb = sh[base + mh];
            float tr = w.x * bb.x - w.y * bb.y;
            float ti = w.x * bb.y + w.y * bb.x;
            sh[base]      = make_float2(a.x + tr, a.y + ti);
            sh[base + mh] = make_float2(a.x - tr, a.y - ti);
        }
        __syncthreads();
    }
}

__global__ void k_rfft(const float* __restrict__ x) {
    __shared__ float2 sh[NT];
    int row = blockIdx.x;
    int b = row >> 7, c = row & 127;
    const float* xp = x + (size_t)row * NT;
    for (int n = threadIdx.x; n < NT; n += blockDim.x)
        sh[__brev(n) >> (32 - LOGN)] = make_float2(xp[n], 0.f);
    __syncthreads();
    fft4096<false>(sh, threadIdx.x, blockDim.x);
    const float inv = 1.0f / SQRTN;
    for (int f = threadIdx.x; f < NF; f += blockDim.x) {
        float2 v = sh[f];
        g_X[((size_t)b * NF + f) * CH + c] = make_float2(v.x * inv, v.y * inv);
    }
}

// ---------------- K/V projection ----------------
__global__ void k_proj(const float* __restrict__ bK, const float* __restrict__ bV) {
    __shared__ float2 xs[16 * CH];
    int r0 = blockIdx.x * 16;
    int tid = threadIdx.x;
    for (int idx = tid; idx < 16 * CH; idx += 256) {
        int r = idx >> 7, c = idx & 127;
        int gr = r0 + r;
        xs[idx] = (gr < MROWS) ? g_X[(size_t)gr * CH + c] : make_float2(0.f, 0.f);
    }
    __syncthreads();
    int cp = tid & 127;
    int half = tid >> 7;
    float kr[8] = {0}, ki[8] = {0}, vr[8] = {0}, vi[8] = {0};
    const float* wk = g_WT;
    const float* wv = g_WT + CH * CH;
    for (int c = 0; c < CH; c++) {
        float a = __ldg(wk + c * CH + cp);
        float bb = __ldg(wv + c * CH + cp);
        #pragma unroll
        for (int r = 0; r < 8; r++) {
            float2 xv = xs[(half * 8 + r) * CH + c];
            kr[r] += xv.x * a;  ki[r] += xv.y * a;
            vr[r] += xv.x * bb; vi[r] += xv.y * bb;
        }
    }
    #pragma unroll
    for (int r = 0; r < 8; r++) {
        int gr = r0 + half * 8 + r;
        if (gr < MROWS) {
            if (gr % NF == 0) { kr[r] += SQRTN * bK[cp]; vr[r] += SQRTN * bV[cp]; }
            g_Kp[(size_t)gr * CH + cp] = make_float2(kr[r], ki[r]);
            g_Vp[(size_t)gr * CH + cp] = make_float2(vr[r], vi[r]);
        }
    }
}

// ---------------- pack staging buffers (tf32-pre-rounded fp32; coalesced) ----------------
__global__ void k_pack() {
    int f = blockIdx.x, b = blockIdx.y, n = threadIdx.x;   // n in [0,256)
    size_t o = ((size_t)b * FP + f) * 256 + n;
    float q = 0.f, kr = 0.f, ki = 0.f, vv = 0.f;
    if (f < NF) {
        int c = n & 127;
        size_t src = ((size_t)b * NF + f) * CH + c;
        float2 X = g_X[src], K = g_Kp[src], V = g_Vp[src];
        if (n < 128) { q = X.x; kr = K.x;  ki = K.y; vv = V.x; }
        else         { q = X.y; kr = -K.y; ki = K.x; vv = V.y; }
    }
    g_Qf[o]  = tf32r(q * SCALE);
    g_Krf[o] = tf32r(kr);
    g_Kif[o] = tf32r(ki);
    g_Vf[o]  = tf32r(vv);
}

// ---------------- tiled transpose of V: g_Vf (FPx256) -> g_VfT (256xFP) ----------------
__global__ void k_vt() {
    __shared__ float t[32][33];
    int b = blockIdx.z;
    int f0 = blockIdx.x * 32, n0 = blockIdx.y * 32;
    int x = threadIdx.x, y = threadIdx.y;    // block (32, 8)
    #pragma unroll
    for (int i = 0; i < 32; i += 8)
        t[y + i][x] = g_Vf[((size_t)b * FP + f0 + y + i) * 256 + n0 + x];
    __syncthreads();
    #pragma unroll
    for (int i = 0; i < 32; i += 8)
        g_VfT[((size_t)b * 256 + n0 + y + i) * FP + f0 + x] = t[x][y + i];
}

// ---------------- energy / median / quantile ----------------
__global__ void k_energy() {
    int row = blockIdx.x;
    int c = threadIdx.x;
    float2 v = g_X[(size_t)row * CH + c];
    float e = v.x * v.x + v.y * v.y;
    #pragma unroll
    for (int o = 16; o; o >>= 1) e += __shfl_xor_sync(~0u, e, o);
    __shared__ float ws[4];
    if ((c & 31) == 0) ws[c >> 5] = e;
    __syncthreads();
    if (c == 0) g_energy[row] = ws[0] + ws[1] + ws[2] + ws[3];
}

__global__ void k_median() {
    int i = blockIdx.x * blockDim.x + threadIdx.x;
    if (i >= MROWS) return;
    int b = i / NF;
    float e = g_energy[i];
    const float* eb = g_energy + b * NF;
    int less = 0, leq = 0;
    for (int f = 0; f < NF; f++) {
        float v = __ldg(eb + f);
        less += (v < e);
        leq  += (v <= e);
    }
    if (less <= (NF / 2) && (NF / 2) < leq) g_med[b] = e;
}

__global__ void k_norm() {
    int i = blockIdx.x * blockDim.x + threadIdx.x;
    if (i < MROWS) g_norm[i] = g_energy[i] / (g_med[i / NF] + 1e-6f);
}

// histogram over top-16 bits of the (non-negative) float bit pattern: monotonic buckets
__global__ void k_hzero() {
    int i = blockIdx.x * blockDim.x + threadIdx.x;
    if (i < 65536) g_hist[i] = 0;
}
__global__ void k_hist() {
    int i = blockIdx.x * blockDim.x + threadIdx.x;
    if (i < MROWS) atomicAdd(&g_hist[__float_as_uint(g_norm[i]) >> 16], 1u);
}
__global__ void k_hscan(const float* __restrict__ thp) {
    __shared__ unsigned ps[1024];
    int t = threadIdx.x;
    unsigned s = 0;
    #pragma unroll 4
    for (int j = 0; j < 64; j++) s += g_hist[t * 64 + j];
    ps[t] = s;
    __syncthreads();
    for (int off = 1; off < 1024; off <<= 1) {
        unsigned v = (t >= off) ? ps[t - off] : 0;
        __syncthreads();
        ps[t] += v;
        __syncthreads();
    }
    unsigned run = (t == 0) ? 0u : ps[t - 1];
    float q = thp[0];
    int k0 = (int)floorf(q * (float)(MROWS - 1));
    unsigned r0 = (unsigned)k0, r1 = (unsigned)(k0 + 1);
    for (int j = 0; j < 64; j++) {
        unsigned c = g_hist[t * 64 + j];
        if (r0 >= run && r0 < run + c) g_bk[0] = t * 64 + j;
        if (r1 >= run && r1 < run + c) g_bk[1] = t * 64 + j;
        run += c;
    }
}
__global__ void k_qsel(const float* __restrict__ thp) {
    int i = blockIdx.x * blockDim.x + threadIdx.x;
    if (i >= MROWS) return;
    float v = g_norm[i];
    int bb = (int)(__float_as_uint(v) >> 16);
    int bk0 = g_bk[0], bk1 = g_bk[1];
    if (bb != bk0 && bb != bk1) return;
    float q = thp[0];
    int k = (int)floorf(q * (float)(MROWS - 1));
    int less = 0, leq = 0;
    for (int j = 0; j < MROWS; j++) {
        float u = __ldg(g_norm + j);
        less += (u < v);
        leq  += (u <= v);
    }
    if (less <= k && k < leq)         g_qv[0] = v;
    if (less <= k + 1 && k + 1 < leq) g_qv[1] = v;
}

__global__ void k_thr(const float* __restrict__ thp) {
    float q = thp[0];
    float h = q * (float)(MROWS - 1);
    float k = floorf(h);
    g_thr[0] = g_qv[0] + (h - k) * (g_qv[1] - g_qv[0]);
}

// ---------------- scores GEMM: logits = scale*|Q K^T| (1x tf32, 3-stage cp.async) ----------------
// BM=128, BN=64, BK=16. 8 warps as 4x2, warp tile 32x32. Single sync per k-tile.
// grid.x = 33: key cols >= 2112 are never computed (all masked padding).
#define SC_SMEM ((3 * (2560 + 1280 + 1280)) * 4)   // 61440 B
__global__ void __launch_bounds__(256, 2) k_scores() {
    extern __shared__ __align__(16) float dsm[];
    float* As  = dsm;                 // 3 x (128 x 20)
    float* Brs = dsm + 3 * 2560;      // 3 x (64 x 20)
    float* Bis = dsm + 3 * 2560 + 3 * 1280;
    int b = blockIdx.z;
    int row0 = blockIdx.y * 128, col0 = blockIdx.x * 64;
    const float* Qb  = g_Qf  + ((size_t)b * FP + row0) * 256;
    const float* Krb = g_Krf + ((size_t)b * FP + col0) * 256;
    const float* Kib = g_Kif + ((size_t)b * FP + col0) * 256;
    int tid = threadIdx.x, w = tid >> 5, lane = tid & 31;
    int g = lane >> 2, t = lane & 3;
    int wr = (w & 3) * 32, wc = (w >> 2) * 32;
    float sr[2][4][4], si[2][4][4];
    #pragma unroll
    for (int rt = 0; rt < 2; rt++)
        #pragma unroll
        for (int nt = 0; nt < 4; nt++)
            #pragma unroll
            for (int e = 0; e < 4; e++) { sr[rt][nt][e] = 0.f; si[rt][nt][e] = 0.f; }

    int lr = tid >> 2, lc = (tid & 3) * 4;
    uint32_t aA  = (uint32_t)__cvta_generic_to_shared(As);
    uint32_t aBr = (uint32_t)__cvta_generic_to_shared(Brs);
    uint32_t aBi = (uint32_t)__cvta_generic_to_shared(Bis);

    auto issue = [&](int kt) {
        int s = kt % 3, k0 = kt * 16;
        uint32_t dA = aA + (uint32_t)(s * 2560 + lr * 20 + lc) * 4;
        cp16(dA,               Qb + (size_t)lr * 256 + k0 + lc);
        cp16(dA + 64 * 20 * 4, Qb + (size_t)(lr + 64) * 256 + k0 + lc);
        cp16(aBr + (uint32_t)(s * 1280 + lr * 20 + lc) * 4, Krb + (size_t)lr * 256 + k0 + lc);
        cp16(aBi + (uint32_t)(s * 1280 + lr * 20 + lc) * 4, Kib + (size_t)lr * 256 + k0 + lc);
        cp_commit();
    };

    issue(0);
    issue(1);
    for (int kt = 0; kt < 16; kt++) {
        if (kt == 15) cp_wait<0>(); else cp_wait<1>();
        __syncthreads();
        if (kt + 2 < 16) issue(kt + 2);
        const float* Ac  = As  + (kt % 3) * 2560;
        const float* Brc = Brs + (kt % 3) * 1280;
        const float* Bic = Bis + (kt % 3) * 1280;
        #pragma unroll
        for (int k8 = 0; k8 < 16; k8 += 8) {
            float a0[2], a1[2], a2[2], a3[2];
            #pragma unroll
            for (int rt = 0; rt < 2; rt++) {
                int r = wr + rt * 16 + g;
                a0[rt] = Ac[r * 20 + k8 + t];
                a1[rt] = Ac[(r + 8) * 20 + k8 + t];
                a2[rt] = Ac[r * 20 + k8 + t + 4];
                a3[rt] = Ac[(r + 8) * 20 + k8 + t + 4];
            }
            #pragma unroll
            for (int nt = 0; nt < 4; nt++) {
                int n = wc + nt * 8 + g;
                float br0 = Brc[n * 20 + k8 + t], br1 = Brc[n * 20 + k8 + t + 4];
                float bi0 = Bic[n * 20 + k8 + t], bi1 = Bic[n * 20 + k8 + t + 4];
                #pragma unroll
                for (int rt = 0; rt < 2; rt++) {
                    mma_tf32(sr[rt][nt], a0[rt], a1[rt], a2[rt], a3[rt], br0, br1);
                    mma_tf32(si[rt][nt], a0[rt], a1[rt], a2[rt], a3[rt], bi0, bi1);
                }
            }
        }
    }
    float* L = g_LOG + ((size_t)b * FP + row0) * FP + col0;
    #pragma unroll
    for (int rt = 0; rt < 2; rt++)
        #pragma unroll
        for (int nt = 0; nt < 4; nt++)
            #pragma unroll
            for (int half = 0; half < 2; half++) {
                int r = wr + rt * 16 + g + half * 8;
                int c0 = wc + nt * 8 + t * 2;
                float x0 = sr[rt][nt][half * 2 + 0], y0 = si[rt][nt][half * 2 + 0];
                float x1 = sr[rt][nt][half * 2 + 1], y1 = si[rt][nt][half * 2 + 1];
                float v0 = sqrtf(x0 * x0 + y0 * y0);
                float v1 = sqrtf(x1 * x1 + y1 * y1);
                if (col0 + c0 >= NF)     v0 = NEG_INF;
                if (col0 + c0 + 1 >= NF) v1 = NEG_INF;
                *(float2*)&L[(size_t)r * FP + c0] = make_float2(v0, v1);
            }
}

// ---------------- row softmax, normalized, store tf32-rounded fp32 ----------------
__global__ void __launch_bounds__(256) k_softmax() {
    int f = blockIdx.x, b = blockIdx.y, tid = threadIdx.x;
    float* Pr = g_P + ((size_t)b * FP + f) * FP;
    if (f >= NF) {
        for (int i = tid; i < FP; i += 256) Pr[i] = 0.f;
        return;
    }
    const float* Lr = g_LOG + ((size_t)b * FP + f) * FP;
    int w = tid >> 5, lane = tid & 31;
    __shared__ float red[8];
    float v[9];
    float m = NEG_INF;
    #pragma unroll
    for (int i = 0; i < 9; i++) {
        int idx = tid + i * 256;
        v[i] = (idx < SC_COLS) ? Lr[idx] : NEG_INF;   // cols >= SC_COLS never written
        m = fmaxf(m, v[i]);
    }
    #pragma unroll
    for (int o = 16; o; o >>= 1) m = fmaxf(m, __shfl_xor_sync(~0u, m, o));
    if (lane == 0) red[w] = m;
    __syncthreads();
    float M = red[0];
    #pragma unroll
    for (int i = 1; i < 8; i++) M = fmaxf(M, red[i]);
    float s = 0.f;
    #pragma unroll
    for (int i = 0; i < 9; i++) {
        float e = __expf(v[i] - M);
        v[i] = e;
        s += e;
    }
    #pragma unroll
    for (int o = 16; o; o >>= 1) s += __shfl_xor_sync(~0u, s, o);
    __syncthreads();
    if (lane == 0) red[w] = s;
    __syncthreads();
    float S = 0.f;
    #pragma unroll
    for (int i = 0; i < 8; i++) S += red[i];
    float inv = 1.0f / S;
    #pragma unroll
    for (int i = 0; i < 9; i++) {
        int idx = tid + i * 256;
        if (idx < FP) Pr[idx] = tf32r(v[i] * inv);
    }
}

// ---------------- PV GEMM: ctx = P * Vt^T (1x tf32, pre-rounded) ----------------
// BM=64, BN=256 (full N -> P read exactly once). BK=16, 3-stage cp.async.
// NK=132: P cols >= 2112 are exact zeros, skipping them is bit-identical.
#define PV_SMEM ((3 * (64 * 20 + 256 * 20)) * 4)
__global__ void __launch_bounds__(256) k_pv() {
    extern __shared__ __align__(16) float dsm[];
    float* As = dsm;                 // 3 x (64 x 20)
    float* Bs = dsm + 3 * 1280;      // 3 x (256 x 20)
    int b = blockIdx.z, row0 = blockIdx.y * 64;
    const float* Pb  = g_P   + ((size_t)b * FP + row0) * FP;
    const float* Vtb = g_VfT + (size_t)b * 256 * FP;
    int tid = threadIdx.x, w = tid >> 5, lane = tid & 31;
    int g = lane >> 2, t = lane & 3;
    int wr = (w & 1) * 32, wc = (w >> 1) * 64;
    float acc[2][8][4];
    #pragma unroll
    for (int rt = 0; rt < 2; rt++)
        #pragma unroll
        for (int nt = 0; nt < 8; nt++)
            #pragma unroll
            for (int e = 0; e < 4; e++) acc[rt][nt][e] = 0.f;

    int lr = tid >> 2, lc = (tid & 3) * 4;   // lr in [0,64), lc in {0,4,8,12}
    uint32_t aA = (uint32_t)__cvta_generic_to_shared(As);
    uint32_t aB = (uint32_t)__cvta_generic_to_shared(Bs);

    auto issue = [&](int kt) {
        int s = kt % 3, k0 = kt * 16;
        cp16(aA + (uint32_t)(s * 1280 + lr * 20 + lc) * 4,
             Pb + (size_t)lr * FP + k0 + lc);
        #pragma unroll
        for (int i = 0; i < 4; i++) {
            int n = lr + 64 * i;
            cp16(aB + (uint32_t)(s * 5120 + n * 20 + lc) * 4,
                 Vtb + (size_t)n * FP + k0 + lc);
        }
        cp_commit();
    };

    const int NK = SC_COLS / 16;   // 132
    issue(0);
    issue(1);
    for (int kt = 0; kt < NK; kt++) {
        if (kt == NK - 1) cp_wait<0>(); else cp_wait<1>();
        __syncthreads();
        if (kt + 2 < NK) issue(kt + 2);
        const float* Ac = As + (kt % 3) * 1280;
        const float* Bc = Bs + (kt % 3) * 5120;
        #pragma unroll
        for (int k8 = 0; k8 < 16; k8 += 8) {
            float a0[2], a1[2], a2[2], a3[2];
            #pragma unroll
            for (int rt = 0; rt < 2; rt++) {
                int r = wr + rt * 16 + g;
                a0[rt] = Ac[r * 20 + k8 + t];
                a1[rt] = Ac[(r + 8) * 20 + k8 + t];
                a2[rt] = Ac[r * 20 + k8 + t + 4];
                a3[rt] = Ac[(r + 8) * 20 + k8 + t + 4];
            }
            #pragma unroll
            for (int nt = 0; nt < 8; nt++) {
                int n = wc + nt * 8 + g;
                float b0 = Bc[n * 20 + k8 + t];
                float b1 = Bc[n * 20 + k8 + t + 4];
                #pragma unroll
                for (int rt = 0; rt < 2; rt++)
                    mma_tf32(acc[rt][nt], a0[rt], a1[rt], a2[rt], a3[rt], b0, b1);
            }
        }
    }
    float* O = g_ctxr + ((size_t)b * FP + row0) * 256;
    #pragma unroll
    for (int rt = 0; rt < 2; rt++)
        #pragma unroll
        for (int nt = 0; nt < 8; nt++)
            #pragma unroll
            for (int half = 0; half < 2; half++) {
                int r = wr + rt * 16 + g + half * 8;
                int c0 = wc + nt * 8 + t * 2;
                *(float2*)&O[(size_t)r * 256 + c0] =
                    make_float2(acc[rt][nt][half * 2 + 0], acc[rt][nt][half * 2 + 1]);
            }
}

// ---------------- combine: high-freq residual + pack into g_ctx ----------------
__global__ void k_combine(const float* __restrict__ whigh) {
    int f = blockIdx.x, b = blockIdx.y, c = threadIdx.x;   // c in [0,128)
    size_t ro = ((size_t)b * FP + f) * 256;
    float cr = g_ctxr[ro + c];
    float ci = g_ctxr[ro + 128 + c];
    if (g_norm[b * NF + f] > g_thr[0]) {
        float2 xv = g_X[((size_t)b * NF + f) * CH + c];
        float wrr = whigh[c * 2], wi = whigh[c * 2 + 1];
        cr += xv.x * wrr - xv.y * wi;
        ci += xv.x * wi + xv.y * wrr;
    }
    g_ctx[((size_t)b * NF + f) * CH + c] = make_float2(cr, ci);
}

// ---------------- irfft ----------------
__global__ void k_irfft(float* __restrict__ out) {
    __shared__ float2 sh[NT];
    int row = blockIdx.x;
    int b = row >> 7, c = row & 127;
    size_t base = ((size_t)b * NF) * CH + c;
    for (int n = threadIdx.x; n < NT; n += blockDim.x) {
        float2 v;
        if (n == 0)            { v = g_ctx[base]; v.y = 0.f; }
        else if (n < NT / 2)   { v = g_ctx[base + (size_t)n * CH]; }
        else if (n == NT / 2)  { v = g_ctx[base + (size_t)(NT / 2) * CH]; v.y = 0.f; }
        else                   { v = g_ctx[base + (size_t)(NT - n) * CH]; v.y = -v.y; }
        sh[__brev(n) >> (32 - LOGN)] = v;
    }
    __syncthreads();
    fft4096<true>(sh, threadIdx.x, blockDim.x);
    float* op = out + (size_t)row * NT;
    const float inv = 1.0f / SQRTN;
    for (int n = threadIdx.x; n < NT; n += blockDim.x)
        op[n] = sh[n].x * inv;
}

// ---------------- launch ----------------
extern "C" void kernel_launch(void* const* d_in, const int* in_sizes, int n_in,
                              void* d_out, int out_size) {
    const float* x   = (const float*)d_in[0];
    const float* WK  = (const float*)d_in[1];
    const float* bK  = (const float*)d_in[2];
    const float* WV  = (const float*)d_in[3];
    const float* bV  = (const float*)d_in[4];
    const float* wh  = (const float*)d_in[5];
    const float* thp = (const float*)d_in[6];
    float* out = (float*)d_out;

    cudaFuncSetAttribute(k_scores, cudaFuncAttributeMaxDynamicSharedMemorySize, SC_SMEM);
    cudaFuncSetAttribute(k_pv, cudaFuncAttributeMaxDynamicSharedMemorySize, PV_SMEM);

    k_init<<<64, 256>>>(WK, WV);
    k_rfft<<<BATCH * CH, 256>>>(x);
    k_proj<<<(MROWS + 15) / 16, 256>>>(bK, bV);
    k_pack<<<dim3(FP, BATCH), 256>>>();
    k_vt<<<dim3(FP / 32, 256 / 32, BATCH), dim3(32, 8)>>>();
    k_scores<<<dim3(SC_COLS / 64, FP / 128, BATCH), 256, SC_SMEM>>>();
    k_energy<<<MROWS, 128>>>();
    k_median<<<(MROWS + 255) / 256, 256>>>();
    k_norm<<<(MROWS + 255) / 256, 256>>>();
    k_hzero<<<256, 256>>>();
    k_hist<<<(MROWS + 255) / 256, 256>>>();
    k_hscan<<<1, 1024>>>(thp);
    k_qsel<<<(MROWS + 255) / 256, 256>>>(thp);
    k_thr<<<1, 1>>>(thp);
    k_softmax<<<dim3(FP, BATCH), 256>>>();
    k_pv<<<dim3(1, FP / 64, BATCH), 256, PV_SMEM>>>();
    k_combine<<<dim3(NF, BATCH), 128>>>(wh);
    k_irfft<<<BATCH * CH, 256>>>(out);
}